// round 5
// baseline (speedup 1.0000x reference)
#include <cuda_runtime.h>
#include <cuda_bf16.h>
#include <math.h>
#include <stdint.h>

// ---------------- problem constants ----------------
#define Dn    64
#define Pn    32
#define NMC   16
#define NG    512           // Pn*NMC
#define NOBS  2048
// output layout (floats)
#define OFF_RECONS 0
#define OFF_LOGP   4096
#define OFF_QZ     4128
#define OFF_QMU    6176
#define OFF_QLV    8224
#define OFF_GHARD  10272
#define OFF_ZNEW   141344

// ---------------- device scratch ----------------
static __device__ double             g_xbar[Dn];
static __device__ float              g_R[Dn * Dn];
static __device__ float              g_probs[Pn * Dn * Dn];
static __device__ unsigned long long g_cols[NG * Dn];   // MC graph: bit i of [g*64+j] = g[i,j]
static __device__ unsigned long long g_colsh[Pn * Dn];  // hard graph columns
static __device__ double             g_ns[NG * Dn];     // per-node scores (MC)
static __device__ double             g_nsh[Pn * Dn];    // per-node scores (hard)
static __device__ double             g_logp[NG];
static __device__ double             g_logph[Pn];
static __device__ double             g_w[NG];
static __device__ float              g_B[Pn * Dn * Dn];
static __device__ float              g_grads[Pn * Dn * Dn * 2];
static __device__ float              g_Kmat[Pn * Pn];
static __device__ unsigned int       g_keys[4];         // sk0 sk1 rk0 rk1
static __device__ double             g_lgtab[64];
static __device__ double             g_logitpe;

// ---------------- threefry2x32 (JAX-exact) ----------------
__device__ __forceinline__ void tf2x32(unsigned k0, unsigned k1,
                                       unsigned x0, unsigned x1,
                                       unsigned &o0, unsigned &o1) {
    unsigned ks0 = k0, ks1 = k1, ks2 = k0 ^ k1 ^ 0x1BD11BDAu;
    x0 += ks0; x1 += ks1;
#define TFR(r) { x0 += x1; x1 = __funnelshift_l(x1, x1, r); x1 ^= x0; }
    TFR(13) TFR(15) TFR(26) TFR(6)   x0 += ks1; x1 += ks2 + 1u;
    TFR(17) TFR(29) TFR(16) TFR(24)  x0 += ks2; x1 += ks0 + 2u;
    TFR(13) TFR(15) TFR(26) TFR(6)   x0 += ks0; x1 += ks1 + 3u;
    TFR(17) TFR(29) TFR(16) TFR(24)  x0 += ks1; x1 += ks2 + 4u;
    TFR(13) TFR(15) TFR(26) TFR(6)   x0 += ks2; x1 += ks0 + 5u;
#undef TFR
    o0 = x0; o1 = x1;
}

// partitionable random_bits (32-bit): element idx -> o0 ^ o1 of tf(key; hi32(idx), lo32(idx))
__device__ __forceinline__ unsigned jax_bits32(unsigned k0, unsigned k1, unsigned idx) {
    unsigned o0, o1;
    tf2x32(k0, k1, 0u, idx, o0, o1);
    return o0 ^ o1;
}

__device__ __forceinline__ float u01f(unsigned b) {
    return __uint_as_float((b >> 9) | 0x3f800000u) - 1.0f;
}

// jax.random.normal: u = max(lo, u01*2 + lo), lo = nextafter(-1,0); sqrt(2)*erfinv(u)
// erfinv via XLA's Giles polynomial (f32).
__device__ __forceinline__ float jax_normal(unsigned bits) {
    const float lo = -0.99999994f;
    float f = u01f(bits);
    float u = fmaxf(lo, fmaf(f, 2.0f, lo));
    float w = -log1pf(-u * u);
    float p;
    if (w < 5.0f) {
        w -= 2.5f;
        p = 2.81022636e-08f;
        p = fmaf(p, w, 3.43273939e-07f);
        p = fmaf(p, w, -3.5233877e-06f);
        p = fmaf(p, w, -4.39150654e-06f);
        p = fmaf(p, w, 0.00021858087f);
        p = fmaf(p, w, -0.00125372503f);
        p = fmaf(p, w, -0.00417768164f);
        p = fmaf(p, w, 0.246640727f);
        p = fmaf(p, w, 1.50140941f);
    } else {
        w = sqrtf(w) - 3.0f;
        p = -0.000200214257f;
        p = fmaf(p, w, 0.000100950558f);
        p = fmaf(p, w, 0.00134934322f);
        p = fmaf(p, w, -0.00367342844f);
        p = fmaf(p, w, 0.00573950773f);
        p = fmaf(p, w, -0.0076224613f);
        p = fmaf(p, w, 0.00943887047f);
        p = fmaf(p, w, 1.00167406f);
        p = fmaf(p, w, 2.83297682f);
    }
    return 1.4142135381698608f * (p * u);
}

// ---------------- init: keys (partitionable fold-like split), lgamma table ----------------
__global__ void init_kernel(const int* seed_ptr) {
    int t = threadIdx.x;
    if (t == 0) {
        unsigned seed = (unsigned)seed_ptr[0];
        // key0 = (0, seed)
        // split(key0): key_i = both outputs of tf(key0; 0, i)
        unsigned a0, a1, b0, b1;
        tf2x32(0u, seed, 0u, 0u, a0, a1);   // new key
        tf2x32(0u, seed, 0u, 1u, b0, b1);   // sk
        unsigned c0, c1, d0, d1;
        tf2x32(a0, a1, 0u, 0u, c0, c1);     // newer key (unused)
        tf2x32(a0, a1, 0u, 1u, d0, d1);     // rk
        g_keys[0] = b0; g_keys[1] = b1;     // sk (bernoulli)
        g_keys[2] = d0; g_keys[3] = d1;     // rk (normal)
        double pe = 4.0 / 63.0;
        g_logitpe = log(pe) - log1p(-pe);
    }
    if (t < 64) {
        const double LOG_PI   = 1.1447298858494001741;
        const double LOG_HALF = -0.6931471805599453094;
        double l = (double)t;
        g_lgtab[t] = -0.5 * log(2049.0)
                   + lgamma(0.5 * (2051.0 + l)) - lgamma(0.5 * (3.0 + l))
                   - 1024.0 * LOG_PI
                   + 0.5 * (3.0 + 2.0 * l) * LOG_HALF;
    }
}

// ---------------- BGe posterior matrix R ----------------
__global__ void xbar_kernel(const float* __restrict__ zgt) {
    int d = threadIdx.x;
    double s = 0.0;
    for (int n = 0; n < NOBS; n++) s += (double)zgt[n * 64 + d];
    g_xbar[d] = s / 2048.0;
}

__global__ void R_kernel(const float* __restrict__ zgt) {
    int i = blockIdx.x, j = threadIdx.x;
    float xi = (float)g_xbar[i], xj = (float)g_xbar[j];
    float acc[8];
#pragma unroll
    for (int r = 0; r < 8; r++) acc[r] = 0.f;
    for (int n = 0; n < NOBS; n += 8) {
#pragma unroll
        for (int r = 0; r < 8; r++)
            acc[r] = fmaf(zgt[(n + r) * 64 + i] - xi, zgt[(n + r) * 64 + j] - xj, acc[r]);
    }
    double s = 0.0;
#pragma unroll
    for (int r = 0; r < 8; r++) s += (double)acc[r];
    s += (2048.0 / 2049.0) * g_xbar[i] * g_xbar[j];
    if (i == j) s += 0.5;
    g_R[i * 64 + j] = (float)s;
}

// ---------------- scores -> probs ----------------
__global__ void scores_kernel(const float* __restrict__ z) {
    int p = blockIdx.x >> 6, i = blockIdx.x & 63, j = threadIdx.x;
    const float* zp = z + p * 8192;
    double acc = 0.0;
    for (int k = 0; k < 64; k++)
        acc += (double)zp[(i * 64 + k) * 2] * (double)zp[(j * 64 + k) * 2 + 1];
    float sc = (float)acc;
    float tl = 0.2f * sc;                       // alpha * score (f32, as ref)
    float pr = (i == j) ? 0.f : (0.5f * tanhf(0.5f * tl) + 0.5f);  // XLA logistic
    g_probs[p * 4096 + i * 64 + j] = pr;
}

// ---------------- bernoulli graph sampling (bitmask columns) ----------------
// bernoulli(sk, probs[:,None], (P,NMC,d,d)): element flat idx -> u01(bits32(sk, idx)) < p
__global__ void bern_kernel() {
    int idx = blockIdx.x * blockDim.x + threadIdx.x;  // 32768 = (p,s,j)
    if (idx >= Pn * NMC * 64) return;
    int j = idx & 63, s = (idx >> 6) & 15, p = idx >> 10;
    unsigned k0 = g_keys[0], k1 = g_keys[1];
    const float* pr = g_probs + p * 4096;
    unsigned base = (unsigned)(((p * 16 + s) * 64) * 64 + j);
    unsigned long long m = 0ull;
    for (int i = 0; i < 64; i++) {
        unsigned bits = jax_bits32(k0, k1, base + (unsigned)(i * 64));
        if (i != j && u01f(bits) < pr[i * 64 + j]) m |= 1ull << i;
    }
    g_cols[(p * 16 + s) * 64 + j] = m;
}

// ---------------- BGe node score: warp-per-(graph,node) Cholesky ----------------
// score_j = lg(l) - 0.5*logdet(R[S,S]) - 0.5*(2051+l)*log(schur pivot of j)
__global__ void bge_kernel(const unsigned long long* __restrict__ cols,
                           double* __restrict__ ns, int ntask) {
    __shared__ float sA[2][64 * 65];
    __shared__ unsigned char sidx[2][64];
    int w = threadIdx.x >> 5, lane = threadIdx.x & 31;
    int task = blockIdx.x * 2 + w;
    if (task >= ntask) return;
    unsigned long long mask = cols[task];
    int l = __popcll(mask);
    int m = l + 1;
    int j = task & 63;
    if (lane == 0) {
        unsigned long long mm = mask; int c = 0;
        while (mm) { int b = __ffsll(mm) - 1; sidx[w][c++] = (unsigned char)b; mm &= mm - 1; }
        sidx[w][l] = (unsigned char)j;
    }
    __syncwarp();
    float* A = sA[w];
    for (int a = 0; a < m; a++) {
        const float* Rrow = g_R + (int)sidx[w][a] * 64;
        for (int b = a + lane; b < m; b += 32) A[a * 65 + b] = Rrow[sidx[w][b]];
    }
    __syncwarp();
    float logA = 0.f, lastpiv = 1.f;
    for (int k = 0; k < m; k++) {
        float piv = A[k * 65 + k];
        if (lane == 0) {
            if (k < m - 1) logA += logf(piv);
            else lastpiv = piv;
        }
        float inv = 1.0f / piv;
        int j0 = k + 1 + lane, j1 = j0 + 32;
        float t0 = 0.f, t1 = 0.f;
        if (j0 < m) t0 = A[k * 65 + j0] * inv;
        if (j1 < m) t1 = A[k * 65 + j1] * inv;
        for (int i = k + 1; i < m; i++) {
            float aki = A[k * 65 + i];
            if (j0 >= i && j0 < m) A[i * 65 + j0] -= aki * t0;
            if (j1 >= i && j1 < m) A[i * 65 + j1] -= aki * t1;
        }
        __syncwarp();
    }
    if (lane == 0) {
        ns[task] = g_lgtab[l] - 0.5 * (double)logA
                 - 0.5 * (2051.0 + (double)l) * log((double)lastpiv);
    }
}

// ---------------- deterministic 64-way reduce ----------------
__global__ void reduce64_kernel(const double* __restrict__ ns, double* __restrict__ out) {
    __shared__ double s[64];
    int g = blockIdx.x, t = threadIdx.x;
    s[t] = ns[g * 64 + t];
    __syncthreads();
    for (int st = 32; st > 0; st >>= 1) {
        if (t < st) s[t] += s[t + st];
        __syncthreads();
    }
    if (t == 0) out[g] = s[0];
}

// ---------------- softmax weights over MC samples ----------------
__global__ void softmax_kernel() {
    int p = blockIdx.x, t = threadIdx.x;
    double v = (t < 16) ? g_logp[p * 16 + t] : -1e300;
    double mx = v;
    for (int o = 16; o > 0; o >>= 1) mx = fmax(mx, __shfl_xor_sync(0xffffffffu, mx, o));
    double e = (t < 16) ? exp(v - mx) : 0.0;
    double sm = e;
    for (int o = 16; o > 0; o >>= 1) sm += __shfl_xor_sync(0xffffffffu, sm, o);
    if (t < 16) g_w[p * 16 + t] = e / sm;
}

// ---------------- B = alpha*(sum_s w_s g_s - probs)*od + Mp ----------------
__global__ void B_kernel() {
    int idx = blockIdx.x * blockDim.x + threadIdx.x;  // 131072
    int j = idx & 63, i = (idx >> 6) & 63, p = idx >> 12;
    float pr = g_probs[p * 4096 + i * 64 + j];
    double ws = 0.0;
    for (int s = 0; s < 16; s++)
        if ((g_cols[(p * 16 + s) * 64 + j] >> i) & 1ull) ws += g_w[p * 16 + s];
    float B = 0.f;
    if (i != j)
        B = 0.2f * ((float)ws - pr) + 0.2f * pr * (1.f - pr) * (float)g_logitpe;
    g_B[idx] = B;
}

// ---------------- grads ----------------
__global__ void gradu_kernel(const float* __restrict__ z) {
    int p = blockIdx.x >> 6, i = blockIdx.x & 63, k = threadIdx.x;
    const float* Bp = g_B + p * 4096 + i * 64;
    const float* zp = z + p * 8192;
    float acc = 0.f;
    for (int j = 0; j < 64; j++) acc = fmaf(Bp[j], zp[(j * 64 + k) * 2 + 1], acc);
    float u = zp[(i * 64 + k) * 2];
    g_grads[(blockIdx.x * 64 + k) * 2] = acc - 64.f * u;
}

__global__ void gradv_kernel(const float* __restrict__ z) {
    int p = blockIdx.x >> 6, j = blockIdx.x & 63, k = threadIdx.x;
    const float* Bp = g_B + p * 4096;
    const float* zp = z + p * 8192;
    float acc = 0.f;
    for (int i = 0; i < 64; i++) acc = fmaf(Bp[i * 64 + j], zp[(i * 64 + k) * 2], acc);
    float v = zp[(j * 64 + k) * 2 + 1];
    g_grads[((p * 64 + j) * 64 + k) * 2 + 1] = acc - 64.f * v;
}

// ---------------- SVGD kernel matrix + update ----------------
__global__ void kmat_kernel(const float* __restrict__ z) {
    int p = blockIdx.x, q = threadIdx.x;
    const float* a = z + p * 8192;
    const float* b = z + q * 8192;
    double sq = 0.0;
    for (int t = 0; t < 8192; t++) {
        double d = (double)a[t] - (double)b[t];
        sq += d * d;
    }
    g_Kmat[p * 32 + q] = (float)exp(-sq / 5.0);
}

__global__ void znew_kernel(const float* __restrict__ z, float* __restrict__ out) {
    int p = blockIdx.x;
    __shared__ float kr[32];
    __shared__ float rowsum;
    if (threadIdx.x < 32) kr[threadIdx.x] = g_Kmat[p * 32 + threadIdx.x];
    __syncthreads();
    if (threadIdx.x == 0) {
        float s = 0.f;
        for (int q = 0; q < 32; q++) s += kr[q];
        rowsum = s;
    }
    __syncthreads();
    for (int d = threadIdx.x; d < 8192; d += blockDim.x) {
        float ag = 0.f, az = 0.f;
        for (int q = 0; q < 32; q++) {
            float kk = kr[q];
            ag = fmaf(kk, g_grads[q * 8192 + d], ag);
            az = fmaf(kk, z[q * 8192 + d], az);
        }
        float zp = z[p * 8192 + d];
        float rep = (-2.0f / 5.0f) * (az - zp * rowsum);
        float zn = zp + 0.005f * ((ag + rep) * (1.0f / 32.0f));
        out[OFF_ZNEW + p * 8192 + d] = zn;
    }
}

// ---------------- hard graphs ----------------
__global__ void s2_kernel(float* __restrict__ out) {
    int p = blockIdx.x >> 6, j = blockIdx.x & 63, i = threadIdx.x;
    __shared__ float vrow[64];
    const float* zn = out + OFF_ZNEW + p * 8192;
    vrow[i] = zn[(j * 64 + i) * 2 + 1];
    __syncthreads();
    double acc = 0.0;
    for (int k = 0; k < 64; k++) acc += (double)zn[(i * 64 + k) * 2] * (double)vrow[k];
    float g = (i != j && acc > 0.0) ? 1.f : 0.f;
    out[OFF_GHARD + p * 4096 + i * 64 + j] = g;
}

__global__ void hmask_kernel(const float* __restrict__ out) {
    int p = blockIdx.x, j = threadIdx.x;
    unsigned long long m = 0ull;
    for (int i = 0; i < 64; i++)
        if (out[OFF_GHARD + p * 4096 + i * 64 + j] > 0.5f) m |= 1ull << i;
    g_colsh[p * 64 + j] = m;
}

__global__ void logpout_kernel(float* __restrict__ out) {
    int p = threadIdx.x;
    out[OFF_LOGP + p] = (float)g_logph[p];
}

// ---------------- encoder/decoder MLPs (single block) ----------------
__global__ void mlp_kernel(float* __restrict__ out,
    const float* ew0, const float* eb0, const float* ew1, const float* eb1,
    const float* ew2, const float* eb2,
    const float* mw0, const float* mb0, const float* mw1, const float* mb1,
    const float* lw0, const float* lb0, const float* lw1, const float* lb1,
    const float* dw0, const float* db0, const float* dw1, const float* db1,
    const float* dw2, const float* db2) {
    __shared__ float bufA[32][128];
    __shared__ float bufB[32][128];
    __shared__ float buf64[32][64];
    int tid = threadIdx.x;
    const float* gh = out + OFF_GHARD;
    // L1: relu(gf2 @ ew0 + eb0) -> [32,20] in bufA
    for (int idx = tid; idx < 32 * 20; idx += 256) {
        int p = idx / 20, o = idx % 20;
        float a = eb0[o];
        const float* gp = gh + p * 4096;
        for (int t = 0; t < 4096; t++) a = fmaf(gp[t], ew0[t * 20 + o], a);
        bufA[p][o] = fmaxf(0.f, a);
    }
    __syncthreads();
    // L2: relu(h0 @ ew1 + eb1) -> [32,64] in bufB
    for (int idx = tid; idx < 2048; idx += 256) {
        int p = idx >> 6, o = idx & 63;
        float a = eb1[o];
        for (int t = 0; t < 20; t++) a = fmaf(bufA[p][t], ew1[t * 64 + o], a);
        bufB[p][o] = fmaxf(0.f, a);
    }
    __syncthreads();
    // L3: relu(h1 @ ew2 + eb2) -> h2 in buf64
    for (int idx = tid; idx < 2048; idx += 256) {
        int p = idx >> 6, o = idx & 63;
        float a = eb2[o];
        for (int t = 0; t < 64; t++) a = fmaf(bufB[p][t], ew2[t * 64 + o], a);
        buf64[p][o] = fmaxf(0.f, a);
    }
    __syncthreads();
    // a_mu = relu(h2 @ mw0 + mb0) -> bufA
    for (int idx = tid; idx < 2048; idx += 256) {
        int p = idx >> 6, o = idx & 63;
        float a = mb0[o];
        for (int t = 0; t < 64; t++) a = fmaf(buf64[p][t], mw0[t * 64 + o], a);
        bufA[p][o] = fmaxf(0.f, a);
    }
    __syncthreads();
    // q_mu = a_mu @ mw1 + mb1 -> bufB + out
    for (int idx = tid; idx < 2048; idx += 256) {
        int p = idx >> 6, o = idx & 63;
        float a = mb1[o];
        for (int t = 0; t < 64; t++) a = fmaf(bufA[p][t], mw1[t * 64 + o], a);
        bufB[p][o] = a;
        out[OFF_QMU + idx] = a;
    }
    __syncthreads();
    // a_lv = relu(h2 @ lw0 + lb0) -> bufA
    for (int idx = tid; idx < 2048; idx += 256) {
        int p = idx >> 6, o = idx & 63;
        float a = lb0[o];
        for (int t = 0; t < 64; t++) a = fmaf(buf64[p][t], lw0[t * 64 + o], a);
        bufA[p][o] = fmaxf(0.f, a);
    }
    __syncthreads();
    // q_lv + eps + q_z -> buf64 + out
    for (int idx = tid; idx < 2048; idx += 256) {
        int p = idx >> 6, o = idx & 63;
        float a = lb1[o];
        for (int t = 0; t < 64; t++) a = fmaf(bufA[p][t], lw1[t * 64 + o], a);
        out[OFF_QLV + idx] = a;
        float eps = jax_normal(jax_bits32(g_keys[2], g_keys[3], (unsigned)idx));
        float qz = bufB[p][o] + eps * expf(0.5f * a);
        out[OFF_QZ + idx] = qz;
        buf64[p][o] = qz;
    }
    __syncthreads();
    // hd0 = relu(q_z @ dw0 + db0) -> [32,10] bufA
    for (int idx = tid; idx < 32 * 10; idx += 256) {
        int p = idx / 10, o = idx % 10;
        float a = db0[o];
        for (int t = 0; t < 64; t++) a = fmaf(buf64[p][t], dw0[t * 10 + o], a);
        bufA[p][o] = fmaxf(0.f, a);
    }
    __syncthreads();
    // hd1 = relu(hd0 @ dw1 + db1) -> [32,128] bufB
    for (int idx = tid; idx < 32 * 128; idx += 256) {
        int p = idx >> 7, o = idx & 127;
        float a = db1[o];
        for (int t = 0; t < 10; t++) a = fmaf(bufA[p][t], dw1[t * 128 + o], a);
        bufB[p][o] = fmaxf(0.f, a);
    }
    __syncthreads();
    // recons = hd1 @ dw2 + db2 -> out
    for (int idx = tid; idx < 32 * 128; idx += 256) {
        int p = idx >> 7, o = idx & 127;
        float a = db2[o];
        for (int t = 0; t < 128; t++) a = fmaf(bufB[p][t], dw2[t * 128 + o], a);
        out[OFF_RECONS + idx] = a;
    }
}

// ---------------- launch ----------------
extern "C" void kernel_launch(void* const* d_in, const int* in_sizes, int n_in,
                              void* d_out, int out_size) {
    const float* z_gt = (const float*)d_in[0];
    const float* z0   = (const float*)d_in[1];
    const float* ew0 = (const float*)d_in[2];  const float* eb0 = (const float*)d_in[3];
    const float* ew1 = (const float*)d_in[4];  const float* eb1 = (const float*)d_in[5];
    const float* ew2 = (const float*)d_in[6];  const float* eb2 = (const float*)d_in[7];
    const float* mw0 = (const float*)d_in[8];  const float* mb0 = (const float*)d_in[9];
    const float* mw1 = (const float*)d_in[10]; const float* mb1 = (const float*)d_in[11];
    const float* lw0 = (const float*)d_in[12]; const float* lb0 = (const float*)d_in[13];
    const float* lw1 = (const float*)d_in[14]; const float* lb1 = (const float*)d_in[15];
    const float* dw0 = (const float*)d_in[16]; const float* db0 = (const float*)d_in[17];
    const float* dw1 = (const float*)d_in[18]; const float* db1 = (const float*)d_in[19];
    const float* dw2 = (const float*)d_in[20]; const float* db2 = (const float*)d_in[21];
    const int*   seed = (const int*)d_in[22];
    float* out = (float*)d_out;

    unsigned long long* colsMC; cudaGetSymbolAddress((void**)&colsMC, g_cols);
    unsigned long long* colsH;  cudaGetSymbolAddress((void**)&colsH,  g_colsh);
    double* nsMC;  cudaGetSymbolAddress((void**)&nsMC,  g_ns);
    double* nsH;   cudaGetSymbolAddress((void**)&nsH,   g_nsh);
    double* logpMC; cudaGetSymbolAddress((void**)&logpMC, g_logp);
    double* logpH;  cudaGetSymbolAddress((void**)&logpH,  g_logph);

    init_kernel<<<1, 64>>>(seed);
    xbar_kernel<<<1, 64>>>(z_gt);
    R_kernel<<<64, 64>>>(z_gt);
    scores_kernel<<<Pn * 64, 64>>>(z0);
    bern_kernel<<<128, 256>>>();
    bge_kernel<<<(NG * 64) / 2, 64>>>(colsMC, nsMC, NG * 64);
    reduce64_kernel<<<NG, 64>>>(nsMC, logpMC);
    softmax_kernel<<<Pn, 32>>>();
    B_kernel<<<512, 256>>>();
    gradu_kernel<<<Pn * 64, 64>>>(z0);
    gradv_kernel<<<Pn * 64, 64>>>(z0);
    kmat_kernel<<<Pn, 32>>>(z0);
    znew_kernel<<<Pn, 256>>>(z0, out);
    s2_kernel<<<Pn * 64, 64>>>(out);
    hmask_kernel<<<Pn, 64>>>(out);
    bge_kernel<<<(Pn * 64) / 2, 64>>>(colsH, nsH, Pn * 64);
    reduce64_kernel<<<Pn, 64>>>(nsH, logpH);
    logpout_kernel<<<1, 32>>>(out);
    mlp_kernel<<<1, 256>>>(out, ew0, eb0, ew1, eb1, ew2, eb2,
                           mw0, mb0, mw1, mb1, lw0, lb0, lw1, lb1,
                           dw0, db0, dw1, db1, dw2, db2);
}